// round 13
// baseline (speedup 1.0000x reference)
#include <cuda_runtime.h>
#include <cuda_fp16.h>

#define BLOCK   128
#define WPB     4
#define NSM     152
#define GOCC    8
#define GBLOCKS (NSM * GOCC)           // 1216
#define GWARPS  (GBLOCKS * WPB)        // 4864
#define SOCC    8
#define SBLOCKS (NSM * SOCC)           // 1216
#define SWARPS  (SBLOCKS * WPB)        // 4864
#define WARM    8
#define PSP     36
#define BMAX    (512 * 1024)

typedef unsigned long long u64;

__device__ unsigned g_M16[(size_t)BMAX * 32];   // fp16x2 m-pair per (step, lane) = 64MB

__device__ __forceinline__ u64 pk2(float a, float b) {
    u64 r; asm("mov.b64 %0, {%1,%2};" : "=l"(r) : "f"(a), "f"(b)); return r;
}
__device__ __forceinline__ void unpk2(float& a, float& b, u64 r) {
    asm("mov.b64 {%0,%1}, %2;" : "=f"(a), "=f"(b) : "l"(r));
}
__device__ __forceinline__ u64 fma2(u64 a, u64 b, u64 c) {
    u64 d; asm("fma.rn.f32x2 %0, %1, %2, %3;" : "=l"(d) : "l"(a), "l"(b), "l"(c)); return d;
}
__device__ __forceinline__ float ftanh(float x) {
    float r; asm("tanh.approx.f32 %0, %1;" : "=f"(r) : "f"(x)); return r;
}
__device__ __forceinline__ void cpa16(unsigned d, const void* s) {
    asm volatile("cp.async.ca.shared.global [%0], [%1], 16;" :: "r"(d), "l"(s));
}
__device__ __forceinline__ void cpacommit() { asm volatile("cp.async.commit_group;"); }
__device__ __forceinline__ void cpawait0()  { asm volatile("cp.async.wait_group 0;"); }

// ───────────────────────── Kernel 1: dependency-free matvec (GEMM) ─────────
__global__ void __launch_bounds__(BLOCK, GOCC) gemm_kernel(
    const float* __restrict__ x, const float* __restrict__ weight,
    const float* __restrict__ weight_y, const float* __restrict__ bias,
    int B, int Lg)
{
    __shared__ __align__(16) float xs[WPB][2][16][16];

    const int w    = threadIdx.x >> 5;
    const int lane = threadIdx.x & 31;
    const int wid  = blockIdx.x * WPB + w;
    const int s0   = wid * Lg;
    if (s0 >= B) return;
    const int s1 = min(s0 + Lg, B);
    const int nt = (s1 - s0 + 15) >> 4;

    const float SC = 0.5f;   // sigma(y)=0.5+0.5*tanh(y/2): z=y/2; fold 0.5 into W,bias
    const int h0 = 2 * lane, h1 = 2 * lane + 1;
    u64 w0k[8], w1k[8];
#pragma unroll
    for (int k = 0; k < 8; k++) {
        const float* r0 = weight + (2 * k) * 64;
        const float* r1 = weight + (2 * k + 1) * 64;
        w0k[k] = pk2(SC * r0[h0], SC * r1[h1]);
        w1k[k] = pk2(SC * r0[h1], SC * r1[h0]);
    }
    // m includes SC*bias + 0.25*wy (the constant part of the folded recurrence)
    const u64 binit0 = pk2(SC * bias[0] + 0.25f * weight_y[h0], 0.f);
    const u64 binit1 = pk2(SC * bias[0] + 0.25f * weight_y[h1], 0.f);

    auto issue = [&](int tb, int st) {
#pragma unroll
        for (int r = 0; r < 2; r++) {
            int slot = lane + r * 32;
            int row = slot >> 2, q = slot & 3;
            int t = min(tb + row, B - 1);
            cpa16((unsigned)__cvta_generic_to_shared(&xs[w][st][row][q * 4]),
                  x + (size_t)t * 64 + q * 4);
        }
    };

    auto matvecR = [&](const float* xrow, float& m0, float& m1) {
        const ulonglong2* xr = (const ulonglong2*)(xrow);
        ulonglong2 qa = xr[0], qb = xr[1], qc = xr[2], qd = xr[3];
        u64 c0 = binit0, c1 = binit1;
        c0 = fma2(qa.x, w0k[0], c0);  c1 = fma2(qa.x, w1k[0], c1);
        c0 = fma2(qa.y, w0k[1], c0);  c1 = fma2(qa.y, w1k[1], c1);
        c0 = fma2(qb.x, w0k[2], c0);  c1 = fma2(qb.x, w1k[2], c1);
        c0 = fma2(qb.y, w0k[3], c0);  c1 = fma2(qb.y, w1k[3], c1);
        c0 = fma2(qc.x, w0k[4], c0);  c1 = fma2(qc.x, w1k[4], c1);
        c0 = fma2(qc.y, w0k[5], c0);  c1 = fma2(qc.y, w1k[5], c1);
        c0 = fma2(qd.x, w0k[6], c0);  c1 = fma2(qd.x, w1k[6], c1);
        c0 = fma2(qd.y, w0k[7], c0);  c1 = fma2(qd.y, w1k[7], c1);
        float a0, b0, a1, b1;
        unpk2(a0, b0, c0);
        unpk2(a1, b1, c1);
        m0 = a0 + b1;
        m1 = a1 + b0;
    };

    issue(s0, 0);
    cpacommit();
    cpawait0();
    __syncwarp();

    int tb = s0;
    for (int k = 0; k < nt; k++) {
        const int st = k & 1;
        if (k + 1 < nt) { issue(tb + 16, st ^ 1); cpacommit(); }

        const int n = min(16, s1 - tb);
        const float (*xa)[16] = xs[w][st];
#pragma unroll
        for (int j = 0; j < 16; j++) {
            if (j < n) {
                float m0, m1;
                matvecR(xa[j], m0, m1);                 // no serial chain anywhere
                __half2 h = __floats2half2_rn(m0, m1);
                g_M16[(size_t)(tb + j) * 32 + lane] = *reinterpret_cast<unsigned*>(&h);
            }
        }
        if (k + 1 < nt) { cpawait0(); __syncwarp(); }
        tb += 16;
    }
}

// ───────────────────────── Kernel 2: feather-weight scan ───────────────────
__global__ void __launch_bounds__(BLOCK, SOCC) scan_kernel(
    const float* __restrict__ weight_y, const float* __restrict__ weight_ln,
    const float* __restrict__ bias_ln, float* __restrict__ out, int B, int L)
{
    __shared__ __align__(16) unsigned ms[WPB][2][16 * 32];   // m tiles, double-buffered
    __shared__ __align__(16) float ps[WPB][16][PSP];         // partials, single buffer

    const int w    = threadIdx.x >> 5;
    const int lane = threadIdx.x & 31;
    const int wid  = blockIdx.x * WPB + w;
    const int start = wid * L;
    if (start >= B) return;
    const int tstop = min(start + L, B);
    const int t0    = max(0, start - WARM);   // contraction warmup (<=0.25^8)
    const int nt    = (tstop - t0 + 15) >> 4;

    const int h0 = 2 * lane, h1 = 2 * lane + 1;
    const float wyt0 = 0.25f * weight_y[h0];
    const float wyt1 = 0.25f * weight_y[h1];
    const float hl0  = 0.5f * weight_ln[h0];
    const float hl1  = 0.5f * weight_ln[h1];
    const float hsum = hl0 + hl1;
    const float bln  = bias_ln[0];

    float z0 = 0.f, z1 = 0.f;
    float t0s = -1.f, t1s = -1.f;    // t = 2s-1; s_init = 0 -> t = -1

    // m tile in gmem is CONTIGUOUS: g_M16[tb*32 .. (tb+16)*32) = 2KB
    auto issueM = [&](int tb, int st) {
        const unsigned* src = g_M16 + (size_t)tb * 32 + lane * 4;
        unsigned dst = (unsigned)__cvta_generic_to_shared(&ms[w][st][lane * 4]);
#pragma unroll
        for (int r = 0; r < 4; r++)
            cpa16(dst + r * 512, src + r * 128);
    };

    // per-step serial part only: 2 FFMA + 2 TANH + partial store
    auto recur = [&](float m0, float m1, int j) {
        z0 = fmaf(wyt0, t0s, m0);
        z1 = fmaf(wyt1, t1s, m1);
        t0s = ftanh(z0);
        t1s = ftanh(z1);
        ps[w][j][lane] = fmaf(hl1, t1s, fmaf(hl0, t0s, hsum));
    };

    const int jj   = lane & 15;
    const int half = lane >> 4;

    auto reducePS = [&](int tb_) {
        const float4* pr = (const float4*)(&ps[w][jj][half * 16]);
        float4 a0 = pr[0], a1 = pr[1], a2 = pr[2], a3 = pr[3];
        float r0 = ((a0.x + a0.y) + (a0.z + a0.w)) + ((a1.x + a1.y) + (a1.z + a1.w));
        float r1 = ((a2.x + a2.y) + (a2.z + a2.w)) + ((a3.x + a3.y) + (a3.z + a3.w));
        float r = r0 + r1;
        r += __shfl_xor_sync(0xffffffffu, r, 16);
        int t = tb_ + jj;
        if (half == 0 && t >= start && t < tstop)
            out[t] = bln + r;
    };

    issueM(t0, 0);
    cpacommit();
    cpawait0();
    __syncwarp();

    unsigned mu = ms[w][0][lane];   // step t0's m-pair
    int tb = t0;

    for (int k = 0; k < nt; k++) {
        const int st = k & 1;
        if (k + 1 < nt) { issueM(tb + 16, st ^ 1); cpacommit(); }

        const int n = min(16, tstop - tb);
        const unsigned* ma = ms[w][st];

        if (n == 16) {
#pragma unroll
            for (int j = 0; j < 16; j++) {
                unsigned mn;
                if (j < 15) mn = ma[(j + 1) * 32 + lane];    // prefetch next m
                float2 mf = __half22float2(*reinterpret_cast<__half2*>(&mu));
                recur(mf.x, mf.y, j);
                if (j < 15) mu = mn;
            }
        } else {
            for (int j = 0; j < n; j++) {
                unsigned mc = ma[j * 32 + lane];
                float2 mf = __half22float2(*reinterpret_cast<__half2*>(&mc));
                recur(mf.x, mf.y, j);
            }
        }
        __syncwarp();

        reducePS(tb);

        if (k + 1 < nt) {
            cpawait0();
            __syncwarp();                 // also orders ps reuse (single buffer)
            mu = ms[w][st ^ 1][lane];     // first m of next tile
        }
        tb += 16;
    }

    // Unique last chunk writes final carries: y_h = 2z, y_hs = 0.5 + 0.5*t
    if (start + L >= B) {
        *(float2*)(out + B + 2 * lane) = make_float2(2.f * z0, 2.f * z1);
        *(float2*)(out + B + 64 + 2 * lane) =
            make_float2(fmaf(0.5f, t0s, 0.5f), fmaf(0.5f, t1s, 0.5f));
    }
}

extern "C" void kernel_launch(void* const* d_in, const int* in_sizes, int n_in,
                              void* d_out, int out_size)
{
    const float* x   = (const float*)d_in[0];
    const float* wt  = (const float*)d_in[1];
    const float* wy  = (const float*)d_in[2];
    const float* b   = (const float*)d_in[3];
    const float* wln = (const float*)d_in[4];
    const float* bln = (const float*)d_in[5];
    float* out = (float*)d_out;

    const int B  = in_sizes[0] / 64;               // x is (B, T=4, I=16); row stride 64
    const int Lg = (B + GWARPS - 1) / GWARPS;      // GEMM steps per warp
    const int L  = (B + SWARPS - 1) / SWARPS;      // scan steps per chunk

    gemm_kernel<<<GBLOCKS, BLOCK>>>(x, wt, wy, b, B, Lg);
    scan_kernel<<<SBLOCKS, BLOCK>>>(wy, wln, bln, out, B, L);
}

// round 14
// speedup vs baseline: 1.2255x; 1.2255x over previous
#include <cuda_runtime.h>

#define BLOCK   128
#define NSM     152
#define OCC     6
#define NBLOCKS (NSM * OCC)     // 912 blocks = 912 chunks (one chunk per BLOCK)
#define WARM    8
#define PH      48              // steps per phase = 3 gemm warps x 16
#define PSP     36

typedef unsigned long long u64;

__device__ __forceinline__ u64 pk2(float a, float b) {
    u64 r; asm("mov.b64 %0, {%1,%2};" : "=l"(r) : "f"(a), "f"(b)); return r;
}
__device__ __forceinline__ void unpk2(float& a, float& b, u64 r) {
    asm("mov.b64 {%0,%1}, %2;" : "=f"(a), "=f"(b) : "l"(r));
}
__device__ __forceinline__ u64 fma2(u64 a, u64 b, u64 c) {
    u64 d; asm("fma.rn.f32x2 %0, %1, %2, %3;" : "=l"(d) : "l"(a), "l"(b), "l"(c)); return d;
}
__device__ __forceinline__ float ftanh(float x) {
    float r; asm("tanh.approx.f32 %0, %1;" : "=f"(r) : "f"(x)); return r;
}
__device__ __forceinline__ void cpa16(unsigned d, const void* s) {
    asm volatile("cp.async.ca.shared.global [%0], [%1], 16;" :: "r"(d), "l"(s));
}
__device__ __forceinline__ void cpacommit() { asm volatile("cp.async.commit_group;"); }
__device__ __forceinline__ void cpawait0()  { asm volatile("cp.async.wait_group 0;"); }
__device__ __forceinline__ void barsync()   { asm volatile("bar.sync 0, 128;" ::: "memory"); }

__global__ void __launch_bounds__(BLOCK, OCC) rnn_ws_kernel(
    const float* __restrict__ x, const float* __restrict__ weight,
    const float* __restrict__ weight_y, const float* __restrict__ bias,
    const float* __restrict__ weight_ln, const float* __restrict__ bias_ln,
    float* __restrict__ out, int B, int L)
{
    __shared__ __align__(16) float  xs[2][PH][16];    // x rows, double-buffered  (6KB)
    __shared__ __align__(16) float2 ms[2][PH][32];    // m pairs, double-buffered (24KB)
    __shared__ __align__(16) float  ps[16][PSP];      // scan-warp partials      (2.25KB)

    const int w    = threadIdx.x >> 5;
    const int lane = threadIdx.x & 31;
    const int start = blockIdx.x * L;                 // one chunk per BLOCK
    if (start >= B) return;
    const int tstop = min(start + L, B);
    const int t0    = max(0, start - WARM);           // contraction warmup
    const int np    = (tstop - t0 + PH - 1) / PH;     // phases

    const int scanw  = blockIdx.x & 3;                // rotate scan warp across SMSPs
    const bool isScan = (w == scanw);
    const int g = (w < scanw) ? w : (w - 1);          // gemm warp logical id 0..2

    const float SC = 0.5f;   // sigma(y)=0.5+0.5*tanh(y/2); state t=tanh(z)
    const int h0 = 2 * lane, h1 = 2 * lane + 1;

    if (!isScan) {
        // ───────── GEMM warps: pure matvec streams, no serial chain ─────────
        u64 w0k[8], w1k[8];
#pragma unroll
        for (int k = 0; k < 8; k++) {
            const float* r0 = weight + (2 * k) * 64;
            const float* r1 = weight + (2 * k + 1) * 64;
            w0k[k] = pk2(SC * r0[h0], SC * r1[h1]);
            w1k[k] = pk2(SC * r0[h1], SC * r1[h0]);
        }
        const u64 binit0 = pk2(SC * bias[0] + 0.25f * weight_y[h0], 0.f);
        const u64 binit1 = pk2(SC * bias[0] + 0.25f * weight_y[h1], 0.f);

        auto issueX = [&](int it) {
            const int base = t0 + it * PH + 16 * g;
            const int buf  = it & 1;
#pragma unroll
            for (int r = 0; r < 2; r++) {
                int slot = lane + r * 32;             // 64 slots = 16 rows x 4 quarters
                int row = slot >> 2, q = slot & 3;
                int t = min(base + row, B - 1);
                cpa16((unsigned)__cvta_generic_to_shared(&xs[buf][16 * g + row][q * 4]),
                      x + (size_t)t * 64 + q * 4);
            }
        };

        issueX(0);
        cpacommit();

        for (int it = 0; it <= np; it++) {
            if (it < np) {
                cpawait0();
                __syncwarp();
                const int buf = it & 1;
                const float (*xa)[16] = xs[buf];
#pragma unroll
                for (int j = 0; j < 16; j++) {
                    const ulonglong2* xr = (const ulonglong2*)(&xa[16 * g + j][0]);
                    ulonglong2 qa = xr[0], qb = xr[1], qc = xr[2], qd = xr[3];
                    u64 c0 = binit0, c1 = binit1;
                    c0 = fma2(qa.x, w0k[0], c0);  c1 = fma2(qa.x, w1k[0], c1);
                    c0 = fma2(qa.y, w0k[1], c0);  c1 = fma2(qa.y, w1k[1], c1);
                    c0 = fma2(qb.x, w0k[2], c0);  c1 = fma2(qb.x, w1k[2], c1);
                    c0 = fma2(qb.y, w0k[3], c0);  c1 = fma2(qb.y, w1k[3], c1);
                    c0 = fma2(qc.x, w0k[4], c0);  c1 = fma2(qc.x, w1k[4], c1);
                    c0 = fma2(qc.y, w0k[5], c0);  c1 = fma2(qc.y, w1k[5], c1);
                    c0 = fma2(qd.x, w0k[6], c0);  c1 = fma2(qd.x, w1k[6], c1);
                    c0 = fma2(qd.y, w0k[7], c0);  c1 = fma2(qd.y, w1k[7], c1);
                    float a0, b0, a1, b1;
                    unpk2(a0, b0, c0);
                    unpk2(a1, b1, c1);
                    ms[buf][16 * g + j][lane] = make_float2(a0 + b1, a1 + b0);
                }
                if (it + 1 < np) { issueX(it + 1); cpacommit(); }
            }
            barsync();   // phase boundary: publish m[it], scan may consume next phase
        }
    } else {
        // ───────── Scan warp: recur + reduce only ─────────
        const float wyt0 = 0.25f * weight_y[h0];
        const float wyt1 = 0.25f * weight_y[h1];
        const float hl0  = 0.5f * weight_ln[h0];
        const float hl1  = 0.5f * weight_ln[h1];
        const float hsum = hl0 + hl1;
        const float bln  = bias_ln[0];

        float z0 = 0.f, z1 = 0.f;
        float t0s = -1.f, t1s = -1.f;     // t = 2s-1; s_init = 0 -> t = -1

        const int jj   = lane & 15;
        const int half = lane >> 4;

        auto reducePS = [&](int tb_) {
            const float4* pr = (const float4*)(&ps[jj][half * 16]);
            float4 a0 = pr[0], a1 = pr[1], a2 = pr[2], a3 = pr[3];
            float r0 = ((a0.x + a0.y) + (a0.z + a0.w)) + ((a1.x + a1.y) + (a1.z + a1.w));
            float r1 = ((a2.x + a2.y) + (a2.z + a2.w)) + ((a3.x + a3.y) + (a3.z + a3.w));
            float r = r0 + r1;
            r += __shfl_xor_sync(0xffffffffu, r, 16);
            int t = tb_ + jj;
            if (half == 0 && t >= start && t < tstop)
                out[t] = bln + r;
        };

        for (int it = 0; it <= np; it++) {
            if (it > 0) {
                const int base = t0 + (it - 1) * PH;
                const int buf  = (it - 1) & 1;
                const int nph  = min(PH, tstop - base);
                const float2 (*mb)[32] = ms[buf];
#pragma unroll
                for (int sub = 0; sub < 3; sub++) {
                    const int bs = 16 * sub;
                    const int nn = min(16, nph - bs);
                    if (nn <= 0) break;
                    if (nn == 16) {
                        float2 mu = mb[bs][lane];
#pragma unroll
                        for (int j = 0; j < 16; j++) {
                            float2 mn;
                            if (j < 15) mn = mb[bs + j + 1][lane];  // prefetch next m
                            z0 = fmaf(wyt0, t0s, mu.x);
                            z1 = fmaf(wyt1, t1s, mu.y);
                            t0s = ftanh(z0);
                            t1s = ftanh(z1);
                            ps[j][lane] = fmaf(hl1, t1s, fmaf(hl0, t0s, hsum));
                            if (j < 15) mu = mn;
                        }
                    } else {
                        for (int j = 0; j < nn; j++) {
                            float2 mu = mb[bs + j][lane];
                            z0 = fmaf(wyt0, t0s, mu.x);
                            z1 = fmaf(wyt1, t1s, mu.y);
                            t0s = ftanh(z0);
                            t1s = ftanh(z1);
                            ps[j][lane] = fmaf(hl1, t1s, fmaf(hl0, t0s, hsum));
                        }
                    }
                    __syncwarp();
                    reducePS(base + bs);
                    __syncwarp();
                }
            }
            barsync();   // phase boundary
        }

        // Unique last chunk writes final carries: y_h = 2z, y_hs = 0.5 + 0.5*t
        if (start + L >= B) {
            *(float2*)(out + B + 2 * lane) = make_float2(2.f * z0, 2.f * z1);
            *(float2*)(out + B + 64 + 2 * lane) =
                make_float2(fmaf(0.5f, t0s, 0.5f), fmaf(0.5f, t1s, 0.5f));
        }
    }
}

extern "C" void kernel_launch(void* const* d_in, const int* in_sizes, int n_in,
                              void* d_out, int out_size)
{
    const float* x   = (const float*)d_in[0];
    const float* wt  = (const float*)d_in[1];
    const float* wy  = (const float*)d_in[2];
    const float* b   = (const float*)d_in[3];
    const float* wln = (const float*)d_in[4];
    const float* bln = (const float*)d_in[5];
    float* out = (float*)d_out;

    const int B = in_sizes[0] / 64;                // x is (B, T=4, I=16); row stride 64
    const int L = (B + NBLOCKS - 1) / NBLOCKS;     // steps per BLOCK (one chunk/block)

    rnn_ws_kernel<<<NBLOCKS, BLOCK>>>(x, wt, wy, b, wln, bln, out, B, L);
}